// round 8
// baseline (speedup 1.0000x reference)
#include <cuda_runtime.h>

// Problem constants (match reference)
#define N1 50000
#define N_LAYERS 3
#define N2 (N1 * N_LAYERS)   // 150000
#define E1 800000
#define E2 2400000
#define NE (E1 + E2)         // 3200000
#define D  64
#define LEAKY 0.01f

#define NNODES (N1 + N2)     // 200000 (graph1 nodes, then graph2 nodes)

// scan config
#define SCAN_ITEMS 8
#define SCAN_THREADS 256
#define SCAN_BLOCK (SCAN_ITEMS * SCAN_THREADS)                  // 2048
#define SCAN_NBLOCKS ((NNODES + SCAN_BLOCK - 1) / SCAN_BLOCK)   // 98

// -------- scratch (device globals; no allocations allowed) --------
__device__ __align__(16) float g_fw1[N1 * D];             // 12.8 MB (conv1 table: norm*x@WQ)
__device__ __align__(16) float g_fw2[N_LAYERS * N1 * D];  // 38.4 MB (conv2 tables, layer-scaled)
__device__ __align__(16) int   g_outdeg[NNODES];
__device__ __align__(16) int   g_indeg[NNODES];
__device__ __align__(16) float g_norm_out[NNODES];
__device__ __align__(16) float g_norm_in[NNODES];
__device__ __align__(16) int   g_csr_off[NNODES];
__device__ __align__(16) int   g_cursor[NNODES];
__device__ __align__(16) unsigned g_scan_state[SCAN_NBLOCKS]; // packed {state[31:30], value[29:0]}
__device__ __align__(16) int   g_csr[NE];                 // 12.8 MB: feature-row index per edge

// -------- kernel 1: zero degree counters + scan state --------
__global__ void zero_kernel() {
    const int nt  = gridDim.x * blockDim.x;
    const int tid = blockIdx.x * blockDim.x + threadIdx.x;
    for (int i = tid; i < NNODES; i += nt) { g_outdeg[i] = 0; g_indeg[i] = 0; }
    if (tid < SCAN_NBLOCKS) g_scan_state[tid] = 0u;
}

// -------- kernel 2: degree histograms (int4 vectorized) --------
__global__ void degrees_kernel(const int4* __restrict__ s1, const int4* __restrict__ d1,
                               const int4* __restrict__ s2, const int4* __restrict__ d2) {
    const int t = blockIdx.x * blockDim.x + threadIdx.x;
    if (t < E1 / 4) {
        const int4 s = s1[t], d = d1[t];
        atomicAdd(&g_outdeg[s.x], 1); atomicAdd(&g_outdeg[s.y], 1);
        atomicAdd(&g_outdeg[s.z], 1); atomicAdd(&g_outdeg[s.w], 1);
        atomicAdd(&g_indeg[d.x], 1);  atomicAdd(&g_indeg[d.y], 1);
        atomicAdd(&g_indeg[d.z], 1);  atomicAdd(&g_indeg[d.w], 1);
    }
    if (t < E2 / 4) {
        const int4 s = s2[t], d = d2[t];
        atomicAdd(&g_outdeg[N1 + s.x], 1); atomicAdd(&g_outdeg[N1 + s.y], 1);
        atomicAdd(&g_outdeg[N1 + s.z], 1); atomicAdd(&g_outdeg[N1 + s.w], 1);
        atomicAdd(&g_indeg[N1 + d.x], 1);  atomicAdd(&g_indeg[N1 + d.y], 1);
        atomicAdd(&g_indeg[N1 + d.z], 1);  atomicAdd(&g_indeg[N1 + d.w], 1);
    }
}

// -------- kernel 3: single-pass scan (decoupled lookback) + cursors + norms --------
// All SCAN_NBLOCKS=98 blocks fit in one wave (148 SMs) -> lookback cannot deadlock.
__global__ void scan_onepass_kernel() {
    __shared__ int sdata[SCAN_BLOCK];
    __shared__ int warpsums[8];
    __shared__ int stotal;
    __shared__ int sprefix;

    const int b = blockIdx.x;
    const int t = threadIdx.x;
    const int base_g = b * SCAN_BLOCK;
    const int lane = t & 31;
    const int wid  = t >> 5;

    for (int i = t; i < SCAN_BLOCK; i += SCAN_THREADS) {
        const int gi = base_g + i;
        sdata[i] = (gi < NNODES) ? g_indeg[gi] : 0;
    }
    __syncthreads();

    int v[SCAN_ITEMS];
    int tsum = 0;
    const int lb = t * SCAN_ITEMS;
#pragma unroll
    for (int i = 0; i < SCAN_ITEMS; i++) { v[i] = sdata[lb + i]; tsum += v[i]; }

    int inc = tsum;
#pragma unroll
    for (int off = 1; off < 32; off <<= 1) {
        int n = __shfl_up_sync(0xFFFFFFFFu, inc, off);
        if (lane >= off) inc += n;
    }
    if (lane == 31) warpsums[wid] = inc;
    __syncthreads();

    if (wid == 0) {
        int s = (lane < 8) ? warpsums[lane] : 0;
#pragma unroll
        for (int off = 1; off < 8; off <<= 1) {
            int n = __shfl_up_sync(0xFFFFFFFFu, s, off);
            if (lane >= off) s += n;
        }
        if (lane < 8) warpsums[lane] = s;   // inclusive warp prefix
    }
    __syncthreads();

    const int wprefix = (wid == 0) ? 0 : warpsums[wid - 1];

    // publish block aggregate ASAP (thread 255 has the block total)
    if (t == SCAN_THREADS - 1) {
        const int total = wprefix + inc;
        stotal = total;
        if (b == 0) {
            *(volatile unsigned*)&g_scan_state[0] = (2u << 30) | (unsigned)total;
        } else {
            *(volatile unsigned*)&g_scan_state[b] = (1u << 30) | (unsigned)total;
        }
    }

    // store block-local exclusive per item
    int running = wprefix + inc - tsum;
#pragma unroll
    for (int i = 0; i < SCAN_ITEMS; i++) { sdata[lb + i] = running; running += v[i]; }
    __syncthreads();

    // warp 0: decoupled lookback for exclusive block prefix
    if (wid == 0) {
        int excl = 0;
        if (b > 0) {
            int offset = 0;
            while (true) {
                const int idx = b - 1 - offset - lane;
                unsigned w;
                if (idx >= 0) {
                    do { w = *(volatile unsigned*)&g_scan_state[idx]; } while (w == 0u);
                } else {
                    w = 2u << 30;   // virtual prefix 0 before block 0
                }
                const unsigned fl = __ballot_sync(0xFFFFFFFFu, (w >> 30) == 2u);
                const int firstP = fl ? (__ffs(fl) - 1) : 32;
                int contrib = (lane <= firstP) ? (int)(w & 0x3FFFFFFFu) : 0;
#pragma unroll
                for (int o = 16; o; o >>= 1) contrib += __shfl_down_sync(0xFFFFFFFFu, contrib, o);
                contrib = __shfl_sync(0xFFFFFFFFu, contrib, 0);
                excl += contrib;
                if (fl) break;
                offset += 32;
            }
            if (lane == 0) {
                *(volatile unsigned*)&g_scan_state[b] = (2u << 30) | (unsigned)(excl + stotal);
            }
        }
        if (lane == 0) sprefix = excl;
    }
    __syncthreads();

    const int bp = sprefix;
    // write csr_off, cursor, norms (coalesced)
    for (int i = t; i < SCAN_BLOCK; i += SCAN_THREADS) {
        const int gi = base_g + i;
        if (gi < NNODES) {
            const int off = sdata[i] + bp;
            g_csr_off[gi] = off;
            g_cursor[gi]  = off;
            g_norm_out[gi] = rsqrtf(fmaxf((float)g_outdeg[gi], 1.f));
            g_norm_in[gi]  = rsqrtf(fmaxf((float)g_indeg[gi], 1.f));
        }
    }
}

// -------- CSR fill: counting sort by dst; stores feature-row index only --------
__global__ void fill_kernel(const int4* __restrict__ s1, const int4* __restrict__ d1,
                            const int4* __restrict__ s2, const int4* __restrict__ d2) {
    const int t = blockIdx.x * blockDim.x + threadIdx.x;
    if (t < E1 / 4) {
        const int4 s = s1[t], d = d1[t];
        const int sv[4] = {s.x, s.y, s.z, s.w};
        const int dv[4] = {d.x, d.y, d.z, d.w};
#pragma unroll
        for (int i = 0; i < 4; i++) {
            const int pos = atomicAdd(&g_cursor[dv[i]], 1);
            g_csr[pos] = sv[i];                  // row in g_fw1[0:N1)
        }
    }
    if (t < E2 / 4) {
        const int4 s = s2[t], d = d2[t];
        const int sv[4] = {s.x, s.y, s.z, s.w};
        const int dv[4] = {d.x, d.y, d.z, d.w};
#pragma unroll
        for (int i = 0; i < 4; i++) {
            const int pos = atomicAdd(&g_cursor[N1 + dv[i]], 1);
            g_csr[pos] = sv[i];                  // row in g_fw2[0:3*N1)
        }
    }
}

// -------- GEMM0: g_fw1[r] = norm_out1[r] * (x @ WQ)[r] --------
// 128 threads: ln = tid&15 (4 output cols), g = tid>>4 (8-row chunk). 64 rows/block.
__global__ void gemm0_kernel(const float* __restrict__ x, const float* __restrict__ W) {
    __shared__ float4 sW4[D * (D / 4)];       // 16 KB
    __shared__ float  srow[64 * D];           // 16 KB

    const int tid = threadIdx.x;
    const int ln  = tid & 15;
    const int g   = tid >> 4;                 // 0..7
    const int row0 = blockIdx.x * 64;

    for (int i = tid; i < D * D / 4; i += 128)
        sW4[i] = reinterpret_cast<const float4*>(W)[i];

    const float4 zero4 = make_float4(0.f, 0.f, 0.f, 0.f);
    for (int i = tid; i < 64 * 16; i += 128) {
        const int r = i >> 4, c = i & 15;
        const int gr = row0 + r;
        const float4 val = (gr < N1) ? reinterpret_cast<const float4*>(x)[gr * 16 + c] : zero4;
        *reinterpret_cast<float4*>(&srow[r * D + c * 4]) = val;
    }
    __syncthreads();

    float4 acc[8];
#pragma unroll
    for (int i = 0; i < 8; i++) acc[i] = zero4;

#pragma unroll 4
    for (int k = 0; k < D; k++) {
        const float4 w = sW4[k * 16 + ln];
#pragma unroll
        for (int i = 0; i < 8; i++) {
            const float s = srow[(g * 8 + i) * D + k];
            acc[i].x = fmaf(s, w.x, acc[i].x);
            acc[i].y = fmaf(s, w.y, acc[i].y);
            acc[i].z = fmaf(s, w.z, acc[i].z);
            acc[i].w = fmaf(s, w.w, acc[i].w);
        }
    }

#pragma unroll
    for (int i = 0; i < 8; i++) {
        const int r = row0 + g * 8 + i;
        if (r < N1) {
            const float sc = g_norm_out[r];
            float4 o = acc[i];
            o.x *= sc; o.y *= sc; o.z *= sc; o.w *= sc;
            reinterpret_cast<float4*>(g_fw1)[r * 16 + ln] = o;
        }
    }
}

// -------- fused conv1 tail: gather(g_fw1) + leaky -> GEMM @WM -> 3 scaled tables --------
// 256 threads, 64 nodes per block.
// Phase A: 16 groups x 16 lanes gather 4 nodes each into smem (h1 rows, never globalized)
// Phase B: GEMM rows @ WM (16 col-groups x 4 rows)
// Phase C: write g_fw2[l*N1+r] = norm_out2[l*N1+r] * row, l=0..2
__global__ void conv1tail_kernel(const float* __restrict__ bQ, const float* __restrict__ WM) {
    __shared__ float4 sW4[D * (D / 4)];       // 16 KB
    __shared__ float  srow[64 * D];           // 16 KB

    const int tid = threadIdx.x;
    const int ln  = tid & 15;
    const int grp = tid >> 4;                 // 0..15
    const int row0 = blockIdx.x * 64;

    for (int i = tid; i < D * D / 4; i += 256)
        sW4[i] = reinterpret_cast<const float4*>(WM)[i];

    const float4 b4 = reinterpret_cast<const float4*>(bQ)[ln];
    const float4* f4 = reinterpret_cast<const float4*>(g_fw1);

    // Phase A: gather + epilogue -> smem
#pragma unroll
    for (int r = 0; r < 4; r++) {
        const int node = row0 + r * 16 + grp;
        if (node < N1) {
            const int start = g_csr_off[node];
            const int cnt   = g_indeg[node];
            const float nin = g_norm_in[node];

            float4 a0 = make_float4(0.f, 0.f, 0.f, 0.f);
            float4 a1 = make_float4(0.f, 0.f, 0.f, 0.f);
            int j = start;
            const int end = start + cnt;
            for (; j + 3 < end; j += 4) {
                const int i0 = g_csr[j],     i1 = g_csr[j + 1];
                const int i2 = g_csr[j + 2], i3 = g_csr[j + 3];
                const float4 v0 = f4[i0 * 16 + ln];
                const float4 v1 = f4[i1 * 16 + ln];
                const float4 v2 = f4[i2 * 16 + ln];
                const float4 v3 = f4[i3 * 16 + ln];
                a0.x += v0.x + v1.x;  a0.y += v0.y + v1.y;
                a0.z += v0.z + v1.z;  a0.w += v0.w + v1.w;
                a1.x += v2.x + v3.x;  a1.y += v2.y + v3.y;
                a1.z += v2.z + v3.z;  a1.w += v2.w + v3.w;
            }
            for (; j < end; j++) {
                const float4 v0 = f4[g_csr[j] * 16 + ln];
                a0.x += v0.x; a0.y += v0.y; a0.z += v0.z; a0.w += v0.w;
            }

            float4 o;
            o.x = fmaf(nin, a0.x + a1.x, b4.x);
            o.y = fmaf(nin, a0.y + a1.y, b4.y);
            o.z = fmaf(nin, a0.z + a1.z, b4.z);
            o.w = fmaf(nin, a0.w + a1.w, b4.w);
            o.x = (o.x > 0.f) ? o.x : LEAKY * o.x;
            o.y = (o.y > 0.f) ? o.y : LEAKY * o.y;
            o.z = (o.z > 0.f) ? o.z : LEAKY * o.z;
            o.w = (o.w > 0.f) ? o.w : LEAKY * o.w;
            *reinterpret_cast<float4*>(&srow[(r * 16 + grp) * D + ln * 4]) = o;
        } else {
            *reinterpret_cast<float4*>(&srow[(r * 16 + grp) * D + ln * 4]) =
                make_float4(0.f, 0.f, 0.f, 0.f);
        }
    }
    __syncthreads();

    // Phase B: GEMM -- this thread: output cols ln*4..+3, rows grp*4..+3
    float4 acc[4];
#pragma unroll
    for (int i = 0; i < 4; i++) acc[i] = make_float4(0.f, 0.f, 0.f, 0.f);

#pragma unroll 4
    for (int k = 0; k < D; k++) {
        const float4 w = sW4[k * 16 + ln];
#pragma unroll
        for (int i = 0; i < 4; i++) {
            const float s = srow[(grp * 4 + i) * D + k];
            acc[i].x = fmaf(s, w.x, acc[i].x);
            acc[i].y = fmaf(s, w.y, acc[i].y);
            acc[i].z = fmaf(s, w.z, acc[i].z);
            acc[i].w = fmaf(s, w.w, acc[i].w);
        }
    }

    // Phase C: 3 layer-scaled table writes
#pragma unroll
    for (int i = 0; i < 4; i++) {
        const int r = row0 + grp * 4 + i;
        if (r < N1) {
#pragma unroll
            for (int l = 0; l < N_LAYERS; l++) {
                const float sc = g_norm_out[N1 + l * N1 + r];
                float4 o = acc[i];
                o.x *= sc; o.y *= sc; o.z *= sc; o.w *= sc;
                reinterpret_cast<float4*>(g_fw2)[(l * N1 + r) * 16 + ln] = o;
            }
        }
    }
}

// -------- conv2 gather: out = leaky(nin * sum(g_fw2 rows) + bM) --------
__global__ void gather2_kernel(const float* __restrict__ bias,
                               float* __restrict__ out) {
    const int tid = threadIdx.x;
    const int grp = tid >> 4;
    const int ln  = tid & 15;

    const int node = blockIdx.x * 16 + grp;
    if (node >= N2) return;
    const int gnode = N1 + node;

    const int start = g_csr_off[gnode];
    const int cnt   = g_indeg[gnode];
    const float nin = g_norm_in[gnode];
    const float4 b4 = reinterpret_cast<const float4*>(bias)[ln];

    const float4* f4 = reinterpret_cast<const float4*>(g_fw2);

    float4 a0 = make_float4(0.f, 0.f, 0.f, 0.f);
    float4 a1 = make_float4(0.f, 0.f, 0.f, 0.f);
    int j = start;
    const int end = start + cnt;
    for (; j + 3 < end; j += 4) {
        const int i0 = g_csr[j],     i1 = g_csr[j + 1];
        const int i2 = g_csr[j + 2], i3 = g_csr[j + 3];
        const float4 v0 = f4[i0 * 16 + ln];
        const float4 v1 = f4[i1 * 16 + ln];
        const float4 v2 = f4[i2 * 16 + ln];
        const float4 v3 = f4[i3 * 16 + ln];
        a0.x += v0.x + v1.x;  a0.y += v0.y + v1.y;
        a0.z += v0.z + v1.z;  a0.w += v0.w + v1.w;
        a1.x += v2.x + v3.x;  a1.y += v2.y + v3.y;
        a1.z += v2.z + v3.z;  a1.w += v2.w + v3.w;
    }
    for (; j < end; j++) {
        const float4 v0 = f4[g_csr[j] * 16 + ln];
        a0.x += v0.x; a0.y += v0.y; a0.z += v0.z; a0.w += v0.w;
    }

    float4 o;
    o.x = fmaf(nin, a0.x + a1.x, b4.x);
    o.y = fmaf(nin, a0.y + a1.y, b4.y);
    o.z = fmaf(nin, a0.z + a1.z, b4.z);
    o.w = fmaf(nin, a0.w + a1.w, b4.w);
    o.x = (o.x > 0.f) ? o.x : LEAKY * o.x;
    o.y = (o.y > 0.f) ? o.y : LEAKY * o.y;
    o.z = (o.z > 0.f) ? o.z : LEAKY * o.z;
    o.w = (o.w > 0.f) ? o.w : LEAKY * o.w;

    reinterpret_cast<float4*>(out)[node * 16 + ln] = o;
}

extern "C" void kernel_launch(void* const* d_in, const int* in_sizes, int n_in,
                              void* d_out, int out_size) {
    const float* x    = (const float*)d_in[0];
    const float* WQ   = (const float*)d_in[1];
    const float* bQ   = (const float*)d_in[2];
    const float* WM   = (const float*)d_in[3];
    const float* bM   = (const float*)d_in[4];
    const int*   src1 = (const int*)d_in[5];
    const int*   dst1 = (const int*)d_in[6];
    const int*   src2 = (const int*)d_in[7];
    const int*   dst2 = (const int*)d_in[8];
    float* out = (float*)d_out;

    // 1. zero degree counters + scan state
    zero_kernel<<<200, 256>>>();
    // 2. degrees (4 edges/thread)
    degrees_kernel<<<(E2 / 4 + 255) / 256, 256>>>((const int4*)src1, (const int4*)dst1,
                                                  (const int4*)src2, (const int4*)dst2);
    // 3. single-pass scan -> csr_off + cursors + norms
    scan_onepass_kernel<<<SCAN_NBLOCKS, SCAN_THREADS>>>();
    // 4. CSR fill (indices only)
    fill_kernel<<<(E2 / 4 + 255) / 256, 256>>>((const int4*)src1, (const int4*)dst1,
                                               (const int4*)src2, (const int4*)dst2);
    // 5. g_fw1 = norm_out1 * (x @ WQ)
    gemm0_kernel<<<(N1 + 63) / 64, 128>>>(x, WQ);
    // 6. fused: gather conv1 + leaky + GEMM @WM + 3 scaled tables -> g_fw2
    conv1tail_kernel<<<(N1 + 63) / 64, 256>>>(bQ, WM);
    // 7. conv2 gather -> out
    gather2_kernel<<<(N2 + 15) / 16, 256>>>(bM, out);
}

// round 9
// speedup vs baseline: 1.0785x; 1.0785x over previous
#include <cuda_runtime.h>
#include <cuda_fp16.h>

// Problem constants (match reference)
#define N1 50000
#define N_LAYERS 3
#define N2 (N1 * N_LAYERS)   // 150000
#define E1 800000
#define E2 2400000
#define NE (E1 + E2)         // 3200000
#define D  64
#define LEAKY 0.01f

#define NNODES (N1 + N2)     // 200000 (graph1 nodes, then graph2 nodes)

// scan config
#define SCAN_ITEMS 8
#define SCAN_THREADS 256
#define SCAN_BLOCK (SCAN_ITEMS * SCAN_THREADS)                  // 2048
#define SCAN_NBLOCKS ((NNODES + SCAN_BLOCK - 1) / SCAN_BLOCK)   // 98

// fused-grid block counts
#define NB_GEMM  ((N1 + 63) / 64)              // 782
#define NB_DEG   ((E2 / 4 + 255) / 256)        // 2344
#define NB_FILL  NB_DEG
#define NB_SCALE 256

// -------- scratch (device globals; no allocations allowed) --------
__device__ __align__(16) float  g_fw1[N1 * D];               // 12.8 MB (conv1 table)
__device__ __align__(16) __half g_fw2h[N_LAYERS * N1 * D];   // 19.2 MB (conv2 tables, fp16)
__device__ __align__(16) int    g_outdeg[NNODES];
__device__ __align__(16) int    g_indeg[NNODES];
__device__ __align__(16) float  g_norm_out[NNODES];
__device__ __align__(16) float  g_norm_in[NNODES];
__device__ __align__(16) int    g_csr_off[NNODES];
__device__ __align__(16) int    g_cursor[NNODES];
__device__ __align__(16) unsigned g_scan_state[SCAN_NBLOCKS]; // {state[31:30], value[29:0]}
__device__ __align__(16) int    g_csr[NE];                   // 12.8 MB

// -------- kernel 1: zero degree counters + scan state --------
__global__ void zero_kernel() {
    const int nt  = gridDim.x * blockDim.x;
    const int tid = blockIdx.x * blockDim.x + threadIdx.x;
    for (int i = tid; i < NNODES; i += nt) { g_outdeg[i] = 0; g_indeg[i] = 0; }
    if (tid < SCAN_NBLOCKS) g_scan_state[tid] = 0u;
}

// -------- kernel 2 (fused grid): GEMM0-unscaled blocks + degree blocks --------
// blocks [0, NB_GEMM): g_fw1 = x @ WQ (unscaled; scaled later, after norms exist)
// blocks [NB_GEMM, NB_GEMM+NB_DEG): degree histograms (int4 vectorized)
__global__ void degrees_gemm_kernel(const float* __restrict__ x, const float* __restrict__ WQ,
                                    const int4* __restrict__ s1, const int4* __restrict__ d1,
                                    const int4* __restrict__ s2, const int4* __restrict__ d2) {
    __shared__ float4 sW4[D * (D / 4)];       // 16 KB
    __shared__ float  srow[64 * D];           // 16 KB

    const int tid = threadIdx.x;

    if (blockIdx.x < NB_GEMM) {
        // ---- GEMM path: 256 threads, 64 rows, 16 col-groups x 4 rows ----
        const int ln  = tid & 15;
        const int grp = tid >> 4;             // 0..15
        const int row0 = blockIdx.x * 64;

        for (int i = tid; i < D * D / 4; i += 256)
            sW4[i] = reinterpret_cast<const float4*>(WQ)[i];

        const float4 zero4 = make_float4(0.f, 0.f, 0.f, 0.f);
        for (int i = tid; i < 64 * 16; i += 256) {
            const int r = i >> 4, c = i & 15;
            const int gr = row0 + r;
            const float4 val = (gr < N1) ? reinterpret_cast<const float4*>(x)[gr * 16 + c] : zero4;
            *reinterpret_cast<float4*>(&srow[r * D + c * 4]) = val;
        }
        __syncthreads();

        float4 acc[4];
#pragma unroll
        for (int i = 0; i < 4; i++) acc[i] = zero4;

#pragma unroll 4
        for (int k = 0; k < D; k++) {
            const float4 w = sW4[k * 16 + ln];
#pragma unroll
            for (int i = 0; i < 4; i++) {
                const float s = srow[(grp * 4 + i) * D + k];
                acc[i].x = fmaf(s, w.x, acc[i].x);
                acc[i].y = fmaf(s, w.y, acc[i].y);
                acc[i].z = fmaf(s, w.z, acc[i].z);
                acc[i].w = fmaf(s, w.w, acc[i].w);
            }
        }
#pragma unroll
        for (int i = 0; i < 4; i++) {
            const int r = row0 + grp * 4 + i;
            if (r < N1) reinterpret_cast<float4*>(g_fw1)[r * 16 + ln] = acc[i];
        }
    } else {
        // ---- degrees path ----
        const int t = (blockIdx.x - NB_GEMM) * 256 + tid;
        if (t < E1 / 4) {
            const int4 s = s1[t], d = d1[t];
            atomicAdd(&g_outdeg[s.x], 1); atomicAdd(&g_outdeg[s.y], 1);
            atomicAdd(&g_outdeg[s.z], 1); atomicAdd(&g_outdeg[s.w], 1);
            atomicAdd(&g_indeg[d.x], 1);  atomicAdd(&g_indeg[d.y], 1);
            atomicAdd(&g_indeg[d.z], 1);  atomicAdd(&g_indeg[d.w], 1);
        }
        if (t < E2 / 4) {
            const int4 s = s2[t], d = d2[t];
            atomicAdd(&g_outdeg[N1 + s.x], 1); atomicAdd(&g_outdeg[N1 + s.y], 1);
            atomicAdd(&g_outdeg[N1 + s.z], 1); atomicAdd(&g_outdeg[N1 + s.w], 1);
            atomicAdd(&g_indeg[N1 + d.x], 1);  atomicAdd(&g_indeg[N1 + d.y], 1);
            atomicAdd(&g_indeg[N1 + d.z], 1);  atomicAdd(&g_indeg[N1 + d.w], 1);
        }
    }
}

// -------- kernel 3: single-pass scan (decoupled lookback) + cursors + norms --------
// All SCAN_NBLOCKS=98 blocks fit in one wave (148 SMs) -> lookback cannot deadlock.
__global__ void scan_onepass_kernel() {
    __shared__ int sdata[SCAN_BLOCK];
    __shared__ int warpsums[8];
    __shared__ int stotal;
    __shared__ int sprefix;

    const int b = blockIdx.x;
    const int t = threadIdx.x;
    const int base_g = b * SCAN_BLOCK;
    const int lane = t & 31;
    const int wid  = t >> 5;

    for (int i = t; i < SCAN_BLOCK; i += SCAN_THREADS) {
        const int gi = base_g + i;
        sdata[i] = (gi < NNODES) ? g_indeg[gi] : 0;
    }
    __syncthreads();

    int v[SCAN_ITEMS];
    int tsum = 0;
    const int lb = t * SCAN_ITEMS;
#pragma unroll
    for (int i = 0; i < SCAN_ITEMS; i++) { v[i] = sdata[lb + i]; tsum += v[i]; }

    int inc = tsum;
#pragma unroll
    for (int off = 1; off < 32; off <<= 1) {
        int n = __shfl_up_sync(0xFFFFFFFFu, inc, off);
        if (lane >= off) inc += n;
    }
    if (lane == 31) warpsums[wid] = inc;
    __syncthreads();

    if (wid == 0) {
        int s = (lane < 8) ? warpsums[lane] : 0;
#pragma unroll
        for (int off = 1; off < 8; off <<= 1) {
            int n = __shfl_up_sync(0xFFFFFFFFu, s, off);
            if (lane >= off) s += n;
        }
        if (lane < 8) warpsums[lane] = s;
    }
    __syncthreads();

    const int wprefix = (wid == 0) ? 0 : warpsums[wid - 1];

    if (t == SCAN_THREADS - 1) {
        const int total = wprefix + inc;
        stotal = total;
        if (b == 0) {
            *(volatile unsigned*)&g_scan_state[0] = (2u << 30) | (unsigned)total;
        } else {
            *(volatile unsigned*)&g_scan_state[b] = (1u << 30) | (unsigned)total;
        }
    }

    int running = wprefix + inc - tsum;
#pragma unroll
    for (int i = 0; i < SCAN_ITEMS; i++) { sdata[lb + i] = running; running += v[i]; }
    __syncthreads();

    if (wid == 0) {
        int excl = 0;
        if (b > 0) {
            int offset = 0;
            while (true) {
                const int idx = b - 1 - offset - lane;
                unsigned w;
                if (idx >= 0) {
                    do { w = *(volatile unsigned*)&g_scan_state[idx]; } while (w == 0u);
                } else {
                    w = 2u << 30;
                }
                const unsigned fl = __ballot_sync(0xFFFFFFFFu, (w >> 30) == 2u);
                const int firstP = fl ? (__ffs(fl) - 1) : 32;
                int contrib = (lane <= firstP) ? (int)(w & 0x3FFFFFFFu) : 0;
#pragma unroll
                for (int o = 16; o; o >>= 1) contrib += __shfl_down_sync(0xFFFFFFFFu, contrib, o);
                contrib = __shfl_sync(0xFFFFFFFFu, contrib, 0);
                excl += contrib;
                if (fl) break;
                offset += 32;
            }
            if (lane == 0) {
                *(volatile unsigned*)&g_scan_state[b] = (2u << 30) | (unsigned)(excl + stotal);
            }
        }
        if (lane == 0) sprefix = excl;
    }
    __syncthreads();

    const int bp = sprefix;
    for (int i = t; i < SCAN_BLOCK; i += SCAN_THREADS) {
        const int gi = base_g + i;
        if (gi < NNODES) {
            const int off = sdata[i] + bp;
            g_csr_off[gi] = off;
            g_cursor[gi]  = off;
            g_norm_out[gi] = rsqrtf(fmaxf((float)g_outdeg[gi], 1.f));
            g_norm_in[gi]  = rsqrtf(fmaxf((float)g_indeg[gi], 1.f));
        }
    }
}

// -------- kernel 4 (fused grid): CSR fill blocks + fw1-scaling blocks --------
// blocks [0, NB_FILL): counting sort by dst (index-only entries)
// blocks [NB_FILL, NB_FILL+NB_SCALE): g_fw1[r] *= norm_out1[r]  (grid-stride)
__global__ void fill_scale_kernel(const int4* __restrict__ s1, const int4* __restrict__ d1,
                                  const int4* __restrict__ s2, const int4* __restrict__ d2) {
    const int tid = threadIdx.x;
    if (blockIdx.x < NB_FILL) {
        const int t = blockIdx.x * 256 + tid;
        if (t < E1 / 4) {
            const int4 s = s1[t], d = d1[t];
            const int sv[4] = {s.x, s.y, s.z, s.w};
            const int dv[4] = {d.x, d.y, d.z, d.w};
#pragma unroll
            for (int i = 0; i < 4; i++) {
                const int pos = atomicAdd(&g_cursor[dv[i]], 1);
                g_csr[pos] = sv[i];
            }
        }
        if (t < E2 / 4) {
            const int4 s = s2[t], d = d2[t];
            const int sv[4] = {s.x, s.y, s.z, s.w};
            const int dv[4] = {d.x, d.y, d.z, d.w};
#pragma unroll
            for (int i = 0; i < 4; i++) {
                const int pos = atomicAdd(&g_cursor[N1 + dv[i]], 1);
                g_csr[pos] = sv[i];
            }
        }
    } else {
        // scale path: multiply each fw1 row by its source norm
        const int start = (blockIdx.x - NB_FILL) * 256 + tid;
        const int stride = NB_SCALE * 256;
        float4* fw = reinterpret_cast<float4*>(g_fw1);
        for (int i = start; i < N1 * 16; i += stride) {
            const float sc = g_norm_out[i >> 4];
            float4 v = fw[i];
            v.x *= sc; v.y *= sc; v.z *= sc; v.w *= sc;
            fw[i] = v;
        }
    }
}

// -------- kernel 5: fused conv1 tail: gather(fw1) + leaky -> GEMM @WM -> 3 fp16 tables --------
__global__ void conv1tail_kernel(const float* __restrict__ bQ, const float* __restrict__ WM) {
    __shared__ float4 sW4[D * (D / 4)];       // 16 KB
    __shared__ float  srow[64 * D];           // 16 KB

    const int tid = threadIdx.x;
    const int ln  = tid & 15;
    const int grp = tid >> 4;                 // 0..15
    const int row0 = blockIdx.x * 64;

    for (int i = tid; i < D * D / 4; i += 256)
        sW4[i] = reinterpret_cast<const float4*>(WM)[i];

    const float4 b4 = reinterpret_cast<const float4*>(bQ)[ln];
    const float4* f4 = reinterpret_cast<const float4*>(g_fw1);

    // Phase A: gather + conv1 epilogue -> smem (h1 rows never hit global)
#pragma unroll
    for (int r = 0; r < 4; r++) {
        const int node = row0 + r * 16 + grp;
        float4 o = make_float4(0.f, 0.f, 0.f, 0.f);
        if (node < N1) {
            const int start = g_csr_off[node];
            const int cnt   = g_indeg[node];
            const float nin = g_norm_in[node];

            float4 a0 = make_float4(0.f, 0.f, 0.f, 0.f);
            float4 a1 = make_float4(0.f, 0.f, 0.f, 0.f);
            int j = start;
            const int end = start + cnt;
            for (; j + 3 < end; j += 4) {
                const int i0 = g_csr[j],     i1 = g_csr[j + 1];
                const int i2 = g_csr[j + 2], i3 = g_csr[j + 3];
                const float4 v0 = f4[i0 * 16 + ln];
                const float4 v1 = f4[i1 * 16 + ln];
                const float4 v2 = f4[i2 * 16 + ln];
                const float4 v3 = f4[i3 * 16 + ln];
                a0.x += v0.x + v1.x;  a0.y += v0.y + v1.y;
                a0.z += v0.z + v1.z;  a0.w += v0.w + v1.w;
                a1.x += v2.x + v3.x;  a1.y += v2.y + v3.y;
                a1.z += v2.z + v3.z;  a1.w += v2.w + v3.w;
            }
            for (; j < end; j++) {
                const float4 v0 = f4[g_csr[j] * 16 + ln];
                a0.x += v0.x; a0.y += v0.y; a0.z += v0.z; a0.w += v0.w;
            }

            o.x = fmaf(nin, a0.x + a1.x, b4.x);
            o.y = fmaf(nin, a0.y + a1.y, b4.y);
            o.z = fmaf(nin, a0.z + a1.z, b4.z);
            o.w = fmaf(nin, a0.w + a1.w, b4.w);
            o.x = (o.x > 0.f) ? o.x : LEAKY * o.x;
            o.y = (o.y > 0.f) ? o.y : LEAKY * o.y;
            o.z = (o.z > 0.f) ? o.z : LEAKY * o.z;
            o.w = (o.w > 0.f) ? o.w : LEAKY * o.w;
        }
        *reinterpret_cast<float4*>(&srow[(r * 16 + grp) * D + ln * 4]) = o;
    }
    __syncthreads();

    // Phase B: GEMM @ WM -- output cols ln*4..+3, rows grp*4..+3
    float4 acc[4];
#pragma unroll
    for (int i = 0; i < 4; i++) acc[i] = make_float4(0.f, 0.f, 0.f, 0.f);

#pragma unroll 4
    for (int k = 0; k < D; k++) {
        const float4 w = sW4[k * 16 + ln];
#pragma unroll
        for (int i = 0; i < 4; i++) {
            const float s = srow[(grp * 4 + i) * D + k];
            acc[i].x = fmaf(s, w.x, acc[i].x);
            acc[i].y = fmaf(s, w.y, acc[i].y);
            acc[i].z = fmaf(s, w.z, acc[i].z);
            acc[i].w = fmaf(s, w.w, acc[i].w);
        }
    }

    // Phase C: 3 layer-scaled fp16 table writes (row = 64 halfs = 16 uint2)
    uint2* fw2 = reinterpret_cast<uint2*>(g_fw2h);
#pragma unroll
    for (int i = 0; i < 4; i++) {
        const int r = row0 + grp * 4 + i;
        if (r < N1) {
#pragma unroll
            for (int l = 0; l < N_LAYERS; l++) {
                const float sc = g_norm_out[N1 + l * N1 + r];
                const __half2 h0 = __floats2half2_rn(acc[i].x * sc, acc[i].y * sc);
                const __half2 h1 = __floats2half2_rn(acc[i].z * sc, acc[i].w * sc);
                uint2 u;
                u.x = *reinterpret_cast<const unsigned*>(&h0);
                u.y = *reinterpret_cast<const unsigned*>(&h1);
                fw2[(l * N1 + r) * 16 + ln] = u;
            }
        }
    }
}

// -------- kernel 6: conv2 gather over fp16 table -> fp32 out --------
__global__ void gather2_kernel(const float* __restrict__ bias,
                               float* __restrict__ out) {
    const int tid = threadIdx.x;
    const int grp = tid >> 4;
    const int ln  = tid & 15;

    const int node = blockIdx.x * 16 + grp;
    if (node >= N2) return;
    const int gnode = N1 + node;

    const int start = g_csr_off[gnode];
    const int cnt   = g_indeg[gnode];
    const float nin = g_norm_in[gnode];
    const float4 b4 = reinterpret_cast<const float4*>(bias)[ln];

    const uint2* f2 = reinterpret_cast<const uint2*>(g_fw2h);

    float4 a0 = make_float4(0.f, 0.f, 0.f, 0.f);
    float4 a1 = make_float4(0.f, 0.f, 0.f, 0.f);
    int j = start;
    const int end = start + cnt;
    for (; j + 3 < end; j += 4) {
        const int i0 = g_csr[j],     i1 = g_csr[j + 1];
        const int i2 = g_csr[j + 2], i3 = g_csr[j + 3];
        const uint2 u0 = f2[i0 * 16 + ln];
        const uint2 u1 = f2[i1 * 16 + ln];
        const uint2 u2 = f2[i2 * 16 + ln];
        const uint2 u3 = f2[i3 * 16 + ln];
        const float2 p0 = __half22float2(*reinterpret_cast<const __half2*>(&u0.x));
        const float2 q0 = __half22float2(*reinterpret_cast<const __half2*>(&u0.y));
        const float2 p1 = __half22float2(*reinterpret_cast<const __half2*>(&u1.x));
        const float2 q1 = __half22float2(*reinterpret_cast<const __half2*>(&u1.y));
        const float2 p2 = __half22float2(*reinterpret_cast<const __half2*>(&u2.x));
        const float2 q2 = __half22float2(*reinterpret_cast<const __half2*>(&u2.y));
        const float2 p3 = __half22float2(*reinterpret_cast<const __half2*>(&u3.x));
        const float2 q3 = __half22float2(*reinterpret_cast<const __half2*>(&u3.y));
        a0.x += p0.x + p1.x;  a0.y += p0.y + p1.y;
        a0.z += q0.x + q1.x;  a0.w += q0.y + q1.y;
        a1.x += p2.x + p3.x;  a1.y += p2.y + p3.y;
        a1.z += q2.x + q3.x;  a1.w += q2.y + q3.y;
    }
    for (; j < end; j++) {
        const uint2 u0 = f2[g_csr[j] * 16 + ln];
        const float2 p0 = __half22float2(*reinterpret_cast<const __half2*>(&u0.x));
        const float2 q0 = __half22float2(*reinterpret_cast<const __half2*>(&u0.y));
        a0.x += p0.x; a0.y += p0.y; a0.z += q0.x; a0.w += q0.y;
    }

    float4 o;
    o.x = fmaf(nin, a0.x + a1.x, b4.x);
    o.y = fmaf(nin, a0.y + a1.y, b4.y);
    o.z = fmaf(nin, a0.z + a1.z, b4.z);
    o.w = fmaf(nin, a0.w + a1.w, b4.w);
    o.x = (o.x > 0.f) ? o.x : LEAKY * o.x;
    o.y = (o.y > 0.f) ? o.y : LEAKY * o.y;
    o.z = (o.z > 0.f) ? o.z : LEAKY * o.z;
    o.w = (o.w > 0.f) ? o.w : LEAKY * o.w;

    reinterpret_cast<float4*>(out)[node * 16 + ln] = o;
}

extern "C" void kernel_launch(void* const* d_in, const int* in_sizes, int n_in,
                              void* d_out, int out_size) {
    const float* x    = (const float*)d_in[0];
    const float* WQ   = (const float*)d_in[1];
    const float* bQ   = (const float*)d_in[2];
    const float* WM   = (const float*)d_in[3];
    const float* bM   = (const float*)d_in[4];
    const int*   src1 = (const int*)d_in[5];
    const int*   dst1 = (const int*)d_in[6];
    const int*   src2 = (const int*)d_in[7];
    const int*   dst2 = (const int*)d_in[8];
    float* out = (float*)d_out;

    // 1. zero counters + scan state
    zero_kernel<<<200, 256>>>();
    // 2. fused: x@WQ (unscaled) || degree histograms
    degrees_gemm_kernel<<<NB_GEMM + NB_DEG, 256>>>(x, WQ,
        (const int4*)src1, (const int4*)dst1, (const int4*)src2, (const int4*)dst2);
    // 3. single-pass scan -> csr_off + cursors + norms
    scan_onepass_kernel<<<SCAN_NBLOCKS, SCAN_THREADS>>>();
    // 4. fused: CSR fill || fw1 *= norm_out1
    fill_scale_kernel<<<NB_FILL + NB_SCALE, 256>>>(
        (const int4*)src1, (const int4*)dst1, (const int4*)src2, (const int4*)dst2);
    // 5. fused conv1 tail -> 3 fp16 layer-scaled tables
    conv1tail_kernel<<<(N1 + 63) / 64, 256>>>(bQ, WM);
    // 6. conv2 gather -> out
    gather2_kernel<<<(N2 + 15) / 16, 256>>>(bM, out);
}